// round 9
// baseline (speedup 1.0000x reference)
#include <cuda_runtime.h>
#include <cuda_fp16.h>
#include <cstdint>

// Problem constants
#define BATCH   2
#define S_LEN   4096
#define DMODEL  512
#define NHEAD   8
#define DHEAD   64
#define WNBR    32
#define M_TOT   (BATCH * S_LEN)      // 8192

// ---------------------------------------------------------------------------
// PTX helpers — base sm_103 only (NO tcgen05)
// ---------------------------------------------------------------------------
__device__ __forceinline__ uint32_t smem_to_u32(const void* p) {
    uint32_t a;
    asm("{ .reg .u64 t; cvta.to.shared.u64 t, %1; cvt.u32.u64 %0, t; }" : "=r"(a) : "l"(p));
    return a;
}
__device__ __forceinline__ void ldsm_x4(uint32_t* r, uint32_t addr) {
    asm volatile("ldmatrix.sync.aligned.m8n8.x4.shared.b16 {%0,%1,%2,%3}, [%4];"
                 : "=r"(r[0]), "=r"(r[1]), "=r"(r[2]), "=r"(r[3]) : "r"(addr));
}
__device__ __forceinline__ void mma_f16_16816(float* d, const uint32_t* a,
                                              uint32_t b0, uint32_t b1) {
    asm volatile(
        "mma.sync.aligned.m16n8k16.row.col.f32.f16.f16.f32 "
        "{%0,%1,%2,%3}, {%4,%5,%6,%7}, {%8,%9}, {%0,%1,%2,%3};"
        : "+f"(d[0]), "+f"(d[1]), "+f"(d[2]), "+f"(d[3])
        : "r"(a[0]), "r"(a[1]), "r"(a[2]), "r"(a[3]), "r"(b0), "r"(b1));
}
#define CP_ASYNC16(sa, gp) \
    asm volatile("cp.async.cg.shared.global [%0], [%1], 16;" :: "r"(sa), "l"(gp))
#define CP_COMMIT() asm volatile("cp.async.commit_group;")
#define CP_WAIT2()  asm volatile("cp.async.wait_group 2;")
#define CP_WAIT0()  asm volatile("cp.async.wait_group 0;")

// ---------------------------------------------------------------------------
// Scratch (allocation-free rule: device globals)
// ---------------------------------------------------------------------------
__device__ __align__(256) __half g_q16[M_TOT * DMODEL];   // Q fp16
__device__ __align__(256) __half g_k16[M_TOT * DMODEL];   // K fp16
__device__ __align__(256) __half g_v16[M_TOT * DMODEL];   // V fp16
__device__ __align__(256) __half g_x16[M_TOT * DMODEL];   // x fp16 (later attn-out)
// weights fp16: rows 0..511 Wq, 512..1023 Wk, 1024..1535 Wv, 1536..2047 Wo
__device__ __align__(256) __half g_w16[4 * DMODEL * DMODEL];

// ---------------------------------------------------------------------------
// Fused prep: convert x and the 4 weight matrices to fp16
// ---------------------------------------------------------------------------
#define NX4  (M_TOT * DMODEL / 4)            // 1048576
#define NW4  (DMODEL * DMODEL / 4)           // 65536

__global__ __launch_bounds__(256)
void prep_kernel(const float* __restrict__ x,
                 const float* __restrict__ w0, const float* __restrict__ w1,
                 const float* __restrict__ w2, const float* __restrict__ w3,
                 __half* __restrict__ x16, __half* __restrict__ w16)
{
    int i = blockIdx.x * blockDim.x + threadIdx.x;
    const float* src;
    __half* dst;
    int l;
    if (i < NX4) {
        src = x; dst = x16; l = i;
    } else {
        int j = i - NX4;
        int w = j >> 16;  l = j & (NW4 - 1);
        src = (w == 0) ? w0 : (w == 1) ? w1 : (w == 2) ? w2 : w3;
        dst = w16 + (size_t)w * DMODEL * DMODEL;
    }
    float4 v = ((const float4*)src)[l];
    ((__half2*)dst)[l * 2 + 0] = __floats2half2_rn(v.x, v.y);
    ((__half2*)dst)[l * 2 + 1] = __floats2half2_rn(v.z, v.w);
}

// ---------------------------------------------------------------------------
// Pure fp16 HMMA GEMM: C = A * B^T (row-major, K-major), fp32 accum.
// CTA tile 128(M) x 256(N), BK=32, 256 threads (8 warps), warp grid 2(M)x4(N),
// warp tile 64x64 (register-reuse: MMA:ldsm ratio 4.0).
// 4-stage cp.async pipeline, one __syncthreads per K-chunk. 1 CTA/SM.
// EPI: 0 = fp32 C ; 1 = QKV fp16 (q / k / v selected by n0 block)
// ---------------------------------------------------------------------------
#define ASTRIDE 40
#define ATILE_B (128 * ASTRIDE * 2)   // 10240 B (128 x 32 halves)
#define BTILE_B (256 * ASTRIDE * 2)   // 20480 B (256 x 32 halves)
#define BUF_B   (ATILE_B + BTILE_B)   // 30720
#define NSTAGE  4
#define GEMM_SMEM (NSTAGE * BUF_B)    // 122880

template <int EPI>
__device__ __forceinline__
void gemm_core(const __half* __restrict__ A, const __half* __restrict__ B,
               float* __restrict__ C, __half* __restrict__ Q16,
               __half* __restrict__ K16, __half* __restrict__ V16)
{
    extern __shared__ char smc[];
    const uint32_t sbase = smem_to_u32(smc);
    const int t = threadIdx.x, lane = t & 31, wid = t >> 5;
    const int wm = wid & 1, wn = wid >> 1;
    const int m0 = blockIdx.y * 128;
    const int n0 = blockIdx.x * 256;

    float acc[4][8][4];
#pragma unroll
    for (int mi = 0; mi < 4; mi++)
#pragma unroll
        for (int ni = 0; ni < 8; ni++)
#pragma unroll
            for (int j = 0; j < 4; j++) acc[mi][ni][j] = 0.0f;

    // cp.async coords: 16B chunks; A = 512 chunks (2/thread), B = 1024 (4/thread)
#define LOAD_CHUNK(kc, buf) do { \
    uint32_t bb = sbase + (uint32_t)(buf) * BUF_B; \
    _Pragma("unroll") \
    for (int i = 0; i < 2; i++) { \
        int e = t + i * 256; \
        int row = e >> 2, c8 = (e & 3) * 8; \
        CP_ASYNC16(bb + (uint32_t)(row * ASTRIDE + c8) * 2, \
                   A + (size_t)(m0 + row) * DMODEL + (kc) + c8); \
    } \
    _Pragma("unroll") \
    for (int i = 0; i < 4; i++) { \
        int e = t + i * 256; \
        int row = e >> 2, c8 = (e & 3) * 8; \
        CP_ASYNC16(bb + ATILE_B + (uint32_t)(row * ASTRIDE + c8) * 2, \
                   B + (size_t)(n0 + row) * DMODEL + (kc) + c8); \
    } \
} while (0)

    // Prologue: 3 chunks in flight
    LOAD_CHUNK(0, 0);  CP_COMMIT();
    LOAD_CHUNK(32, 1); CP_COMMIT();
    LOAD_CHUNK(64, 2); CP_COMMIT();

    const int lrow = lane & 15;
    const int lcol = lane >> 4;

    for (int c = 0; c < 16; c++) {
        CP_WAIT2();                    // chunk c resident (2 newer may pend)
        __syncthreads();               // buf (c+3)%4 free
        if (c < 13) LOAD_CHUNK((c + 3) * 32, (c + 3) & 3);
        CP_COMMIT();

        const uint32_t ab = sbase + (uint32_t)(c & 3) * BUF_B;
#pragma unroll
        for (int ks = 0; ks < 2; ks++) {
            uint32_t af[4][4], bf[4][4];
            const int kcol = ks * 2 + lcol;
#pragma unroll
            for (int mi = 0; mi < 4; mi++) {
                uint32_t ad = ab + (uint32_t)(((wm * 64 + mi * 16 + lrow) * ASTRIDE) + kcol * 8) * 2;
                ldsm_x4(af[mi], ad);
            }
#pragma unroll
            for (int nb = 0; nb < 4; nb++) {
                uint32_t bd = ab + ATILE_B +
                              (uint32_t)(((wn * 64 + nb * 16 + lrow) * ASTRIDE) + kcol * 8) * 2;
                ldsm_x4(bf[nb], bd);
            }
#pragma unroll
            for (int mi = 0; mi < 4; mi++)
#pragma unroll
                for (int ni = 0; ni < 8; ni++) {
                    const int nb = ni >> 1, nl = ni & 1;
                    mma_f16_16816(acc[mi][ni], af[mi], bf[nb][nl], bf[nb][nl + 2]);
                }
        }
    }
#undef LOAD_CHUNK

    if (EPI == 0) {
#pragma unroll
        for (int mi = 0; mi < 4; mi++) {
            const int r0 = m0 + wm * 64 + mi * 16 + (lane >> 2);
#pragma unroll
            for (int ni = 0; ni < 8; ni++) {
                const int cc = n0 + wn * 64 + ni * 8 + (lane & 3) * 2;
                *(float2*)(C + (size_t)r0 * DMODEL + cc)       = make_float2(acc[mi][ni][0], acc[mi][ni][1]);
                *(float2*)(C + (size_t)(r0 + 8) * DMODEL + cc) = make_float2(acc[mi][ni][2], acc[mi][ni][3]);
            }
        }
    } else {
        __half* dst;
        int nb0;
        if (n0 < 512)       { dst = Q16; nb0 = n0; }
        else if (n0 < 1024) { dst = K16; nb0 = n0 - 512; }
        else                { dst = V16; nb0 = n0 - 1024; }
#pragma unroll
        for (int mi = 0; mi < 4; mi++) {
            const int r0 = m0 + wm * 64 + mi * 16 + (lane >> 2);
#pragma unroll
            for (int ni = 0; ni < 8; ni++) {
                const int cc = nb0 + wn * 64 + ni * 8 + (lane & 3) * 2;
                *(__half2*)(dst + (size_t)r0 * DMODEL + cc) =
                    __floats2half2_rn(acc[mi][ni][0], acc[mi][ni][1]);
                *(__half2*)(dst + (size_t)(r0 + 8) * DMODEL + cc) =
                    __floats2half2_rn(acc[mi][ni][2], acc[mi][ni][3]);
            }
        }
    }
}

__global__ __launch_bounds__(256, 1)
void gemm_qkv(const __half* __restrict__ A, const __half* __restrict__ B,
              __half* __restrict__ Q16, __half* __restrict__ K16, __half* __restrict__ V16)
{
    gemm_core<1>(A, B, nullptr, Q16, K16, V16);
}

__global__ __launch_bounds__(256, 1)
void gemm_out(const __half* __restrict__ A, const __half* __restrict__ B,
              float* __restrict__ C)
{
    gemm_core<0>(A, B, C, nullptr, nullptr, nullptr);
}

// ---------------------------------------------------------------------------
// Neighbor attention: K staged via cp.async (33 KB smem), V gathered directly
// from L2 per-warp (first 16 rows prefetched before softmax). One CTA per
// (b,s); 8 warps = 8 heads. q fp16 in, output fp16.
// ---------------------------------------------------------------------------
#define PITCH_H 520                          // halves; row stride 1040 B
#define ATT_SMEM (WNBR * PITCH_H * 2)        // 33280 B
#define CP_WAIT0A() asm volatile("cp.async.wait_group 0;")

__global__ __launch_bounds__(256, 6)
void attn_kernel(const __half* __restrict__ q16,
                 const __half* __restrict__ k16,
                 const __half* __restrict__ v16,
                 const int*   __restrict__ nidx,
                 __half* __restrict__ a16)
{
    extern __shared__ char smc[];
    const uint32_t sbase = smem_to_u32(smc);
    __shared__ int   sj[WNBR];
    __shared__ float sq[DMODEL];

    const int bs   = blockIdx.x;
    const int s    = bs & (S_LEN - 1);
    const int b    = bs >> 12;
    const int t    = threadIdx.x;
    const int h    = t >> 5;
    const int lane = t & 31;

    if (t < WNBR) sj[t] = nidx[s * WNBR + t];
    {
        __half2 qh = *(const __half2*)(q16 + (size_t)bs * DMODEL + t * 2);
        float2 qf = __half22float2(qh);
        sq[t * 2]     = qf.x;
        sq[t * 2 + 1] = qf.y;
    }
    __syncthreads();

    // Stage K rows: 32 rows x 1024 B, 64 16B-chunks per row, 8 per thread.
#pragma unroll
    for (int i = 0; i < 8; i++) {
        int e = t + i * 256;
        int w = e >> 6, c = e & 63;
        size_t src = (size_t)(b * S_LEN + sj[w]) * DMODEL + c * 8;
        CP_ASYNC16(sbase + (uint32_t)(w * 1040 + c * 16), k16 + src);
    }
    CP_COMMIT();
    CP_WAIT0A();
    __syncthreads();

    // Scores: lane owns neighbor `lane`
    float acc = 0.0f;
    {
        const char* kr = smc + lane * 1040 + h * 128;
        const float* qr = sq + h * DHEAD;
#pragma unroll
        for (int i = 0; i < 8; i++) {
            uint4 kv = *(const uint4*)(kr + i * 16);
            float4 q0 = *(const float4*)(qr + i * 8);
            float4 q1 = *(const float4*)(qr + i * 8 + 4);
            float2 f0 = __half22float2(*(__half2*)&kv.x);
            float2 f1 = __half22float2(*(__half2*)&kv.y);
            float2 f2 = __half22float2(*(__half2*)&kv.z);
            float2 f3 = __half22float2(*(__half2*)&kv.w);
            acc += q0.x * f0.x + q0.y * f0.y + q0.z * f1.x + q0.w * f1.y
                 + q1.x * f2.x + q1.y * f2.y + q1.z * f3.x + q1.w * f3.y;
        }
    }
    float score = acc * 0.125f;

    // Prefetch V rows 0..15 (depend only on sj) before the softmax chain
    const __half* vbase = v16 + (size_t)b * S_LEN * DMODEL + h * DHEAD + lane * 2;
    float2 vpre[16];
#pragma unroll
    for (int u = 0; u < 16; u++)
        vpre[u] = __half22float2(*(const __half2*)(vbase + (size_t)sj[u] * DMODEL));

    // Warp softmax
    float m = score;
#pragma unroll
    for (int o = 16; o; o >>= 1) m = fmaxf(m, __shfl_xor_sync(0xffffffffu, m, o));
    float e = __expf(score - m);
    float ssum = e;
#pragma unroll
    for (int o = 16; o; o >>= 1) ssum += __shfl_xor_sync(0xffffffffu, ssum, o);
    float p = e / ssum;

    // PV: prefetched rows, then the remaining two 8-deep batches
    float ox = 0.0f, oy = 0.0f;
#pragma unroll
    for (int u = 0; u < 16; u++) {
        float pw = __shfl_sync(0xffffffffu, p, u);
        ox += pw * vpre[u].x;
        oy += pw * vpre[u].y;
    }
#pragma unroll
    for (int w0 = 16; w0 < WNBR; w0 += 8) {
        float2 vv[8];
#pragma unroll
        for (int u = 0; u < 8; u++)
            vv[u] = __half22float2(*(const __half2*)(vbase + (size_t)sj[w0 + u] * DMODEL));
#pragma unroll
        for (int u = 0; u < 8; u++) {
            float pw = __shfl_sync(0xffffffffu, p, w0 + u);
            ox += pw * vv[u].x;
            oy += pw * vv[u].y;
        }
    }

    // fp16 output (feeds final GEMM directly)
    const size_t oidx = (size_t)bs * DMODEL + h * DHEAD + lane * 2;
    *(__half2*)(a16 + oidx) = __floats2half2_rn(ox, oy);
}

// ---------------------------------------------------------------------------
extern "C" void kernel_launch(void* const* d_in, const int* in_sizes, int n_in,
                              void* d_out, int out_size)
{
    const float* x    = (const float*)d_in[0];
    const float* Wq   = (const float*)d_in[1];
    const float* Wk   = (const float*)d_in[2];
    const float* Wv   = (const float*)d_in[3];
    const float* Wo   = (const float*)d_in[4];
    const int*   nidx = (const int*)  d_in[5];
    float*       out  = (float*)d_out;

    __half *q16, *k16, *v16, *x16, *w16;
    cudaGetSymbolAddress((void**)&q16, g_q16);
    cudaGetSymbolAddress((void**)&k16, g_k16);
    cudaGetSymbolAddress((void**)&v16, g_v16);
    cudaGetSymbolAddress((void**)&x16, g_x16);
    cudaGetSymbolAddress((void**)&w16, g_w16);

    static int attr_set = 0;
    if (!attr_set) {
        cudaFuncSetAttribute(attn_kernel, cudaFuncAttributeMaxDynamicSharedMemorySize, ATT_SMEM);
        cudaFuncSetAttribute(gemm_qkv,    cudaFuncAttributeMaxDynamicSharedMemorySize, GEMM_SMEM);
        cudaFuncSetAttribute(gemm_out,    cudaFuncAttributeMaxDynamicSharedMemorySize, GEMM_SMEM);
        attr_set = 1;
    }

    const int NW = DMODEL * DMODEL;           // 262144

    prep_kernel<<<(NX4 + 4 * NW4) / 256, 256>>>(x, Wq, Wk, Wv, Wo, x16, w16);

    dim3 qkvgrid(3 * DMODEL / 256, M_TOT / 128);   // (6, 64) = 384 CTAs
    gemm_qkv<<<qkvgrid, 256, GEMM_SMEM>>>(x16, w16, q16, k16, v16);

    attn_kernel<<<M_TOT, 256, ATT_SMEM>>>(q16, k16, v16, nidx, x16);

    dim3 ogrid(DMODEL / 256, M_TOT / 128);         // (2, 64) = 128 CTAs
    gemm_out<<<ogrid, 256, GEMM_SMEM>>>(x16, w16 + 3 * NW, out);
}

// round 10
// speedup vs baseline: 1.0232x; 1.0232x over previous
#include <cuda_runtime.h>
#include <cuda_fp16.h>
#include <cstdint>

// Problem constants
#define BATCH   2
#define S_LEN   4096
#define DMODEL  512
#define NHEAD   8
#define DHEAD   64
#define WNBR    32
#define M_TOT   (BATCH * S_LEN)      // 8192

// ---------------------------------------------------------------------------
// PTX helpers — base sm_103 only (NO tcgen05)
// ---------------------------------------------------------------------------
__device__ __forceinline__ uint32_t smem_to_u32(const void* p) {
    uint32_t a;
    asm("{ .reg .u64 t; cvta.to.shared.u64 t, %1; cvt.u32.u64 %0, t; }" : "=r"(a) : "l"(p));
    return a;
}
__device__ __forceinline__ void ldsm_x4(uint32_t* r, uint32_t addr) {
    asm volatile("ldmatrix.sync.aligned.m8n8.x4.shared.b16 {%0,%1,%2,%3}, [%4];"
                 : "=r"(r[0]), "=r"(r[1]), "=r"(r[2]), "=r"(r[3]) : "r"(addr));
}
__device__ __forceinline__ void mma_f16_16816(float* d, const uint32_t* a,
                                              uint32_t b0, uint32_t b1) {
    asm volatile(
        "mma.sync.aligned.m16n8k16.row.col.f32.f16.f16.f32 "
        "{%0,%1,%2,%3}, {%4,%5,%6,%7}, {%8,%9}, {%0,%1,%2,%3};"
        : "+f"(d[0]), "+f"(d[1]), "+f"(d[2]), "+f"(d[3])
        : "r"(a[0]), "r"(a[1]), "r"(a[2]), "r"(a[3]), "r"(b0), "r"(b1));
}
#define CP_ASYNC16(sa, gp) \
    asm volatile("cp.async.cg.shared.global [%0], [%1], 16;" :: "r"(sa), "l"(gp))
#define CP_COMMIT() asm volatile("cp.async.commit_group;")
#define CP_WAIT2()  asm volatile("cp.async.wait_group 2;")
#define CP_WAIT0()  asm volatile("cp.async.wait_group 0;")

// ---------------------------------------------------------------------------
// Scratch (allocation-free rule: device globals)
// ---------------------------------------------------------------------------
__device__ __align__(256) __half g_q16[M_TOT * DMODEL];   // Q fp16
__device__ __align__(256) __half g_k16[M_TOT * DMODEL];   // K fp16
__device__ __align__(256) __half g_v16[M_TOT * DMODEL];   // V fp16
__device__ __align__(256) __half g_x16[M_TOT * DMODEL];   // x fp16 (later attn-out)
// weights fp16: rows 0..511 Wq, 512..1023 Wk, 1024..1535 Wv, 1536..2047 Wo
__device__ __align__(256) __half g_w16[4 * DMODEL * DMODEL];

// ---------------------------------------------------------------------------
// Fused prep: convert x and the 4 weight matrices to fp16
// ---------------------------------------------------------------------------
#define NX4  (M_TOT * DMODEL / 4)            // 1048576
#define NW4  (DMODEL * DMODEL / 4)           // 65536

__global__ __launch_bounds__(256)
void prep_kernel(const float* __restrict__ x,
                 const float* __restrict__ w0, const float* __restrict__ w1,
                 const float* __restrict__ w2, const float* __restrict__ w3,
                 __half* __restrict__ x16, __half* __restrict__ w16)
{
    int i = blockIdx.x * blockDim.x + threadIdx.x;
    const float* src;
    __half* dst;
    int l;
    if (i < NX4) {
        src = x; dst = x16; l = i;
    } else {
        int j = i - NX4;
        int w = j >> 16;  l = j & (NW4 - 1);
        src = (w == 0) ? w0 : (w == 1) ? w1 : (w == 2) ? w2 : w3;
        dst = w16 + (size_t)w * DMODEL * DMODEL;
    }
    float4 v = ((const float4*)src)[l];
    ((__half2*)dst)[l * 2 + 0] = __floats2half2_rn(v.x, v.y);
    ((__half2*)dst)[l * 2 + 1] = __floats2half2_rn(v.z, v.w);
}

// ---------------------------------------------------------------------------
// Pure fp16 HMMA GEMM: C = A * B^T (row-major, K-major), fp32 accum.
// CTA 128x128, BK=32, 256 threads, warp grid 2(M) x 4(N), warp tile 64x32.
// 4-stage cp.async pipeline (data ready 3 chunks ahead), one sync per chunk.
// All 12 ldsm for both ks halves issued before any MMA (frag-level ILP).
// EPI: 0 = fp32 C ; 1 = QKV fp16 (q / k / v selected by n0 block)
// ---------------------------------------------------------------------------
#define ASTRIDE 40
#define TILE_B  (128 * ASTRIDE * 2)   // 10240 B per 128x32 tile
#define BUF_B   (2 * TILE_B)          // A|B = 20480
#define NSTAGE  4
#define GEMM_SMEM (NSTAGE * BUF_B)    // 81920

template <int EPI>
__device__ __forceinline__
void gemm_core(const __half* __restrict__ A, const __half* __restrict__ B,
               float* __restrict__ C, __half* __restrict__ Q16,
               __half* __restrict__ K16, __half* __restrict__ V16)
{
    extern __shared__ char smc[];
    const uint32_t sbase = smem_to_u32(smc);
    const int t = threadIdx.x, lane = t & 31, wid = t >> 5;
    const int wm = wid & 1, wn = wid >> 1;
    const int m0 = blockIdx.y * 128;
    const int n0 = blockIdx.x * 128;

    float acc[4][4][4];
#pragma unroll
    for (int mi = 0; mi < 4; mi++)
#pragma unroll
        for (int ni = 0; ni < 4; ni++)
#pragma unroll
            for (int j = 0; j < 4; j++) acc[mi][ni][j] = 0.0f;

    const int e0row = t >> 2,         e0c = (t & 3) * 8;
    const int e1row = (t + 256) >> 2, e1c = ((t + 256) & 3) * 8;
    const uint32_t so0 = (uint32_t)(e0row * ASTRIDE + e0c) * 2;
    const uint32_t so1 = (uint32_t)(e1row * ASTRIDE + e1c) * 2;

#define LOAD_CHUNK(kc, buf) do { \
    uint32_t bb = sbase + (uint32_t)(buf) * BUF_B; \
    size_t ga0 = (size_t)(m0 + e0row) * DMODEL + (kc) + e0c; \
    size_t ga1 = (size_t)(m0 + e1row) * DMODEL + (kc) + e1c; \
    size_t gb0 = (size_t)(n0 + e0row) * DMODEL + (kc) + e0c; \
    size_t gb1 = (size_t)(n0 + e1row) * DMODEL + (kc) + e1c; \
    CP_ASYNC16(bb + so0,          A + ga0); \
    CP_ASYNC16(bb + so1,          A + ga1); \
    CP_ASYNC16(bb + TILE_B + so0, B + gb0); \
    CP_ASYNC16(bb + TILE_B + so1, B + gb1); \
} while (0)

    // Prologue: 3 chunks in flight
    LOAD_CHUNK(0, 0);  CP_COMMIT();
    LOAD_CHUNK(32, 1); CP_COMMIT();
    LOAD_CHUNK(64, 2); CP_COMMIT();

    const int lrow = lane & 15;
    const int lcol = lane >> 4;

    for (int c = 0; c < 16; c++) {
        CP_WAIT2();                    // chunk c resident (2 newer may pend)
        __syncthreads();               // buf (c+3)%4 free for reuse
        if (c < 13) LOAD_CHUNK((c + 3) * 32, (c + 3) & 3);
        CP_COMMIT();

        const uint32_t ab = sbase + (uint32_t)(c & 3) * BUF_B;

        // Issue ALL fragment loads for both ks halves, then all MMAs:
        // the 16 MMAs of ks0 hide the ldsm latency of ks1's fragments.
        uint32_t af0[4][4], bf0[2][4], af1[4][4], bf1[2][4];
        {
            const int k0 = lcol;           // ks0 16B-col
            const int k1 = 2 + lcol;       // ks1 16B-col
#pragma unroll
            for (int mi = 0; mi < 4; mi++) {
                uint32_t ar = ab + (uint32_t)((wm * 64 + mi * 16 + lrow) * ASTRIDE) * 2;
                ldsm_x4(af0[mi], ar + k0 * 16);
                ldsm_x4(af1[mi], ar + k1 * 16);
            }
#pragma unroll
            for (int nb = 0; nb < 2; nb++) {
                uint32_t br = ab + TILE_B + (uint32_t)((wn * 32 + nb * 16 + lrow) * ASTRIDE) * 2;
                ldsm_x4(bf0[nb], br + k0 * 16);
                ldsm_x4(bf1[nb], br + k1 * 16);
            }
        }
#pragma unroll
        for (int mi = 0; mi < 4; mi++)
#pragma unroll
            for (int ni = 0; ni < 4; ni++) {
                const int nb = ni >> 1, nl = ni & 1;
                mma_f16_16816(acc[mi][ni], af0[mi], bf0[nb][nl], bf0[nb][nl + 2]);
            }
#pragma unroll
        for (int mi = 0; mi < 4; mi++)
#pragma unroll
            for (int ni = 0; ni < 4; ni++) {
                const int nb = ni >> 1, nl = ni & 1;
                mma_f16_16816(acc[mi][ni], af1[mi], bf1[nb][nl], bf1[nb][nl + 2]);
            }
    }
#undef LOAD_CHUNK
    CP_WAIT0();

    if (EPI == 0) {
#pragma unroll
        for (int mi = 0; mi < 4; mi++) {
            const int r0 = m0 + wm * 64 + mi * 16 + (lane >> 2);
#pragma unroll
            for (int ni = 0; ni < 4; ni++) {
                const int cc = n0 + wn * 32 + ni * 8 + (lane & 3) * 2;
                *(float2*)(C + (size_t)r0 * DMODEL + cc)       = make_float2(acc[mi][ni][0], acc[mi][ni][1]);
                *(float2*)(C + (size_t)(r0 + 8) * DMODEL + cc) = make_float2(acc[mi][ni][2], acc[mi][ni][3]);
            }
        }
    } else {
        __half* dst;
        int nb0;
        if (n0 < 512)       { dst = Q16; nb0 = n0; }
        else if (n0 < 1024) { dst = K16; nb0 = n0 - 512; }
        else                { dst = V16; nb0 = n0 - 1024; }
#pragma unroll
        for (int mi = 0; mi < 4; mi++) {
            const int r0 = m0 + wm * 64 + mi * 16 + (lane >> 2);
#pragma unroll
            for (int ni = 0; ni < 4; ni++) {
                const int cc = nb0 + wn * 32 + ni * 8 + (lane & 3) * 2;
                *(__half2*)(dst + (size_t)r0 * DMODEL + cc) =
                    __floats2half2_rn(acc[mi][ni][0], acc[mi][ni][1]);
                *(__half2*)(dst + (size_t)(r0 + 8) * DMODEL + cc) =
                    __floats2half2_rn(acc[mi][ni][2], acc[mi][ni][3]);
            }
        }
    }
}

__global__ __launch_bounds__(256, 2)
void gemm_qkv(const __half* __restrict__ A, const __half* __restrict__ B,
              __half* __restrict__ Q16, __half* __restrict__ K16, __half* __restrict__ V16)
{
    gemm_core<1>(A, B, nullptr, Q16, K16, V16);
}

__global__ __launch_bounds__(256, 2)
void gemm_out(const __half* __restrict__ A, const __half* __restrict__ B,
              float* __restrict__ C)
{
    gemm_core<0>(A, B, C, nullptr, nullptr, nullptr);
}

// ---------------------------------------------------------------------------
// Neighbor attention: K staged via cp.async (33 KB smem), V gathered directly
// from L2 per-warp (first 16 rows prefetched before softmax). One CTA per
// (b,s); 8 warps = 8 heads. q fp16 in, output fp16.
// ---------------------------------------------------------------------------
#define PITCH_H 520                          // halves; row stride 1040 B
#define ATT_SMEM (WNBR * PITCH_H * 2)        // 33280 B

__global__ __launch_bounds__(256, 6)
void attn_kernel(const __half* __restrict__ q16,
                 const __half* __restrict__ k16,
                 const __half* __restrict__ v16,
                 const int*   __restrict__ nidx,
                 __half* __restrict__ a16)
{
    extern __shared__ char smc[];
    const uint32_t sbase = smem_to_u32(smc);
    __shared__ int   sj[WNBR];
    __shared__ float sq[DMODEL];

    const int bs   = blockIdx.x;
    const int s    = bs & (S_LEN - 1);
    const int b    = bs >> 12;
    const int t    = threadIdx.x;
    const int h    = t >> 5;
    const int lane = t & 31;

    if (t < WNBR) sj[t] = nidx[s * WNBR + t];
    {
        __half2 qh = *(const __half2*)(q16 + (size_t)bs * DMODEL + t * 2);
        float2 qf = __half22float2(qh);
        sq[t * 2]     = qf.x;
        sq[t * 2 + 1] = qf.y;
    }
    __syncthreads();

    // Stage K rows: 32 rows x 1024 B, 64 16B-chunks per row, 8 per thread.
#pragma unroll
    for (int i = 0; i < 8; i++) {
        int e = t + i * 256;
        int w = e >> 6, c = e & 63;
        size_t src = (size_t)(b * S_LEN + sj[w]) * DMODEL + c * 8;
        CP_ASYNC16(sbase + (uint32_t)(w * 1040 + c * 16), k16 + src);
    }
    CP_COMMIT();
    CP_WAIT0();
    __syncthreads();

    // Scores: lane owns neighbor `lane`
    float acc = 0.0f;
    {
        const char* kr = smc + lane * 1040 + h * 128;
        const float* qr = sq + h * DHEAD;
#pragma unroll
        for (int i = 0; i < 8; i++) {
            uint4 kv = *(const uint4*)(kr + i * 16);
            float4 q0 = *(const float4*)(qr + i * 8);
            float4 q1 = *(const float4*)(qr + i * 8 + 4);
            float2 f0 = __half22float2(*(__half2*)&kv.x);
            float2 f1 = __half22float2(*(__half2*)&kv.y);
            float2 f2 = __half22float2(*(__half2*)&kv.z);
            float2 f3 = __half22float2(*(__half2*)&kv.w);
            acc += q0.x * f0.x + q0.y * f0.y + q0.z * f1.x + q0.w * f1.y
                 + q1.x * f2.x + q1.y * f2.y + q1.z * f3.x + q1.w * f3.y;
        }
    }
    float score = acc * 0.125f;

    // Prefetch V rows 0..15 (depend only on sj) before the softmax chain
    const __half* vbase = v16 + (size_t)b * S_LEN * DMODEL + h * DHEAD + lane * 2;
    float2 vpre[16];
#pragma unroll
    for (int u = 0; u < 16; u++)
        vpre[u] = __half22float2(*(const __half2*)(vbase + (size_t)sj[u] * DMODEL));

    // Warp softmax
    float m = score;
#pragma unroll
    for (int o = 16; o; o >>= 1) m = fmaxf(m, __shfl_xor_sync(0xffffffffu, m, o));
    float e = __expf(score - m);
    float ssum = e;
#pragma unroll
    for (int o = 16; o; o >>= 1) ssum += __shfl_xor_sync(0xffffffffu, ssum, o);
    float p = e / ssum;

    // PV: prefetched rows, then the remaining two 8-deep batches
    float ox = 0.0f, oy = 0.0f;
#pragma unroll
    for (int u = 0; u < 16; u++) {
        float pw = __shfl_sync(0xffffffffu, p, u);
        ox += pw * vpre[u].x;
        oy += pw * vpre[u].y;
    }
#pragma unroll
    for (int w0 = 16; w0 < WNBR; w0 += 8) {
        float2 vv[8];
#pragma unroll
        for (int u = 0; u < 8; u++)
            vv[u] = __half22float2(*(const __half2*)(vbase + (size_t)sj[w0 + u] * DMODEL));
#pragma unroll
        for (int u = 0; u < 8; u++) {
            float pw = __shfl_sync(0xffffffffu, p, w0 + u);
            ox += pw * vv[u].x;
            oy += pw * vv[u].y;
        }
    }

    // fp16 output (feeds final GEMM directly)
    const size_t oidx = (size_t)bs * DMODEL + h * DHEAD + lane * 2;
    *(__half2*)(a16 + oidx) = __floats2half2_rn(ox, oy);
}

// ---------------------------------------------------------------------------
extern "C" void kernel_launch(void* const* d_in, const int* in_sizes, int n_in,
                              void* d_out, int out_size)
{
    const float* x    = (const float*)d_in[0];
    const float* Wq   = (const float*)d_in[1];
    const float* Wk   = (const float*)d_in[2];
    const float* Wv   = (const float*)d_in[3];
    const float* Wo   = (const float*)d_in[4];
    const int*   nidx = (const int*)  d_in[5];
    float*       out  = (float*)d_out;

    __half *q16, *k16, *v16, *x16, *w16;
    cudaGetSymbolAddress((void**)&q16, g_q16);
    cudaGetSymbolAddress((void**)&k16, g_k16);
    cudaGetSymbolAddress((void**)&v16, g_v16);
    cudaGetSymbolAddress((void**)&x16, g_x16);
    cudaGetSymbolAddress((void**)&w16, g_w16);

    static int attr_set = 0;
    if (!attr_set) {
        cudaFuncSetAttribute(attn_kernel, cudaFuncAttributeMaxDynamicSharedMemorySize, ATT_SMEM);
        cudaFuncSetAttribute(gemm_qkv,    cudaFuncAttributeMaxDynamicSharedMemorySize, GEMM_SMEM);
        cudaFuncSetAttribute(gemm_out,    cudaFuncAttributeMaxDynamicSharedMemorySize, GEMM_SMEM);
        attr_set = 1;
    }

    const int NW = DMODEL * DMODEL;           // 262144

    prep_kernel<<<(NX4 + 4 * NW4) / 256, 256>>>(x, Wq, Wk, Wv, Wo, x16, w16);

    dim3 qkvgrid(3 * DMODEL / 128, M_TOT / 128);   // (12, 64) = 768 CTAs
    gemm_qkv<<<qkvgrid, 256, GEMM_SMEM>>>(x16, w16, q16, k16, v16);

    attn_kernel<<<M_TOT, 256, ATT_SMEM>>>(q16, k16, v16, nidx, x16);

    dim3 ogrid(DMODEL / 128, M_TOT / 128);         // (4, 64) = 256 CTAs
    gemm_out<<<ogrid, 256, GEMM_SMEM>>>(x16, w16 + 3 * NW, out);
}

// round 11
// speedup vs baseline: 1.0591x; 1.0351x over previous
#include <cuda_runtime.h>
#include <cuda_fp16.h>
#include <cstdint>

// Problem constants
#define BATCH   2
#define S_LEN   4096
#define DMODEL  512
#define NHEAD   8
#define DHEAD   64
#define WNBR    32
#define M_TOT   (BATCH * S_LEN)      // 8192

// ---------------------------------------------------------------------------
// PTX helpers — base sm_103 only (NO tcgen05)
// ---------------------------------------------------------------------------
__device__ __forceinline__ uint32_t smem_to_u32(const void* p) {
    uint32_t a;
    asm("{ .reg .u64 t; cvta.to.shared.u64 t, %1; cvt.u32.u64 %0, t; }" : "=r"(a) : "l"(p));
    return a;
}
__device__ __forceinline__ void ldsm_x4(uint32_t* r, uint32_t addr) {
    asm volatile("ldmatrix.sync.aligned.m8n8.x4.shared.b16 {%0,%1,%2,%3}, [%4];"
                 : "=r"(r[0]), "=r"(r[1]), "=r"(r[2]), "=r"(r[3]) : "r"(addr));
}
__device__ __forceinline__ void mma_f16_16816(float* d, const uint32_t* a,
                                              uint32_t b0, uint32_t b1) {
    asm volatile(
        "mma.sync.aligned.m16n8k16.row.col.f32.f16.f16.f32 "
        "{%0,%1,%2,%3}, {%4,%5,%6,%7}, {%8,%9}, {%0,%1,%2,%3};"
        : "+f"(d[0]), "+f"(d[1]), "+f"(d[2]), "+f"(d[3])
        : "r"(a[0]), "r"(a[1]), "r"(a[2]), "r"(a[3]), "r"(b0), "r"(b1));
}
#define CP_ASYNC16(sa, gp) \
    asm volatile("cp.async.cg.shared.global [%0], [%1], 16;" :: "r"(sa), "l"(gp))
#define CP_COMMIT() asm volatile("cp.async.commit_group;")
#define CP_WAIT1()  asm volatile("cp.async.wait_group 1;")
#define CP_WAIT0()  asm volatile("cp.async.wait_group 0;")

// ---------------------------------------------------------------------------
// Scratch (allocation-free rule: device globals)
// ---------------------------------------------------------------------------
__device__ __align__(256) __half g_q16[M_TOT * DMODEL];   // Q fp16
__device__ __align__(256) __half g_k16[M_TOT * DMODEL];   // K fp16
__device__ __align__(256) __half g_v16[M_TOT * DMODEL];   // V fp16
__device__ __align__(256) __half g_x16[M_TOT * DMODEL];   // x fp16 (later attn-out)
// weights fp16: rows 0..511 Wq, 512..1023 Wk, 1024..1535 Wv, 1536..2047 Wo
__device__ __align__(256) __half g_w16[4 * DMODEL * DMODEL];

// ---------------------------------------------------------------------------
// Fused prep: convert x and the 4 weight matrices to fp16
// ---------------------------------------------------------------------------
#define NX4  (M_TOT * DMODEL / 4)            // 1048576
#define NW4  (DMODEL * DMODEL / 4)           // 65536

__global__ __launch_bounds__(256)
void prep_kernel(const float* __restrict__ x,
                 const float* __restrict__ w0, const float* __restrict__ w1,
                 const float* __restrict__ w2, const float* __restrict__ w3,
                 __half* __restrict__ x16, __half* __restrict__ w16)
{
    int i = blockIdx.x * blockDim.x + threadIdx.x;
    const float* src;
    __half* dst;
    int l;
    if (i < NX4) {
        src = x; dst = x16; l = i;
    } else {
        int j = i - NX4;
        int w = j >> 16;  l = j & (NW4 - 1);
        src = (w == 0) ? w0 : (w == 1) ? w1 : (w == 2) ? w2 : w3;
        dst = w16 + (size_t)w * DMODEL * DMODEL;
    }
    float4 v = ((const float4*)src)[l];
    ((__half2*)dst)[l * 2 + 0] = __floats2half2_rn(v.x, v.y);
    ((__half2*)dst)[l * 2 + 1] = __floats2half2_rn(v.z, v.w);
}

// ---------------------------------------------------------------------------
// Pure fp16 HMMA GEMM (round-8 proven config): C = A * B^T, fp32 accum.
// CTA 128x128, BK=32, 256 threads, warp grid 2(M) x 4(N), warp tile 64x32.
// 3-stage cp.async pipeline, one __syncthreads per K-chunk. moffs = batch base.
// EPI: 0 = fp32 C ; 1 = QKV fp16 (q / k / v selected by n0 block)
// ---------------------------------------------------------------------------
#define ASTRIDE 40
#define TILE_B  (128 * ASTRIDE * 2)   // 10240 B per 128x32 tile
#define BUF_B   (2 * TILE_B)          // A|B = 20480
#define NSTAGE  3
#define GEMM_SMEM (NSTAGE * BUF_B)    // 61440

template <int EPI>
__device__ __forceinline__
void gemm_core(const __half* __restrict__ A, const __half* __restrict__ B,
               float* __restrict__ C, __half* __restrict__ Q16,
               __half* __restrict__ K16, __half* __restrict__ V16, int moffs)
{
    extern __shared__ char smc[];
    const uint32_t sbase = smem_to_u32(smc);
    const int t = threadIdx.x, lane = t & 31, wid = t >> 5;
    const int wm = wid & 1, wn = wid >> 1;
    const int m0 = moffs + blockIdx.y * 128;
    const int n0 = blockIdx.x * 128;

    float acc[4][4][4];
#pragma unroll
    for (int mi = 0; mi < 4; mi++)
#pragma unroll
        for (int ni = 0; ni < 4; ni++)
#pragma unroll
            for (int j = 0; j < 4; j++) acc[mi][ni][j] = 0.0f;

    const int e0row = t >> 2,         e0c = (t & 3) * 8;
    const int e1row = (t + 256) >> 2, e1c = ((t + 256) & 3) * 8;
    const uint32_t so0 = (uint32_t)(e0row * ASTRIDE + e0c) * 2;
    const uint32_t so1 = (uint32_t)(e1row * ASTRIDE + e1c) * 2;

#define LOAD_CHUNK(kc, buf) do { \
    uint32_t bb = sbase + (uint32_t)(buf) * BUF_B; \
    size_t ga0 = (size_t)(m0 + e0row) * DMODEL + (kc) + e0c; \
    size_t ga1 = (size_t)(m0 + e1row) * DMODEL + (kc) + e1c; \
    size_t gb0 = (size_t)(n0 + e0row) * DMODEL + (kc) + e0c; \
    size_t gb1 = (size_t)(n0 + e1row) * DMODEL + (kc) + e1c; \
    CP_ASYNC16(bb + so0,          A + ga0); \
    CP_ASYNC16(bb + so1,          A + ga1); \
    CP_ASYNC16(bb + TILE_B + so0, B + gb0); \
    CP_ASYNC16(bb + TILE_B + so1, B + gb1); \
} while (0)

    // Prologue: 2 chunks in flight
    LOAD_CHUNK(0, 0);
    CP_COMMIT();
    LOAD_CHUNK(32, 1);
    CP_COMMIT();

    const int lrow = lane & 15;
    const int lcol = lane >> 4;

    for (int c = 0; c < 16; c++) {
        CP_WAIT1();                    // chunk c resident
        __syncthreads();               // buf (c+2)%3 free
        if (c < 14) LOAD_CHUNK((c + 2) * 32, (c + 2) % NSTAGE);
        CP_COMMIT();

        const uint32_t ab = sbase + (uint32_t)(c % NSTAGE) * BUF_B;
#pragma unroll
        for (int ks = 0; ks < 2; ks++) {
            uint32_t af[4][4], bf[2][4];
            const int kcol = ks * 2 + lcol;
#pragma unroll
            for (int mi = 0; mi < 4; mi++) {
                uint32_t ad = ab + (uint32_t)(((wm * 64 + mi * 16 + lrow) * ASTRIDE) + kcol * 8) * 2;
                ldsm_x4(af[mi], ad);
            }
#pragma unroll
            for (int nb = 0; nb < 2; nb++) {
                uint32_t bd = ab + TILE_B +
                              (uint32_t)(((wn * 32 + nb * 16 + lrow) * ASTRIDE) + kcol * 8) * 2;
                ldsm_x4(bf[nb], bd);
            }
#pragma unroll
            for (int mi = 0; mi < 4; mi++)
#pragma unroll
                for (int ni = 0; ni < 4; ni++) {
                    const int nb = ni >> 1, nl = ni & 1;
                    mma_f16_16816(acc[mi][ni], af[mi], bf[nb][nl], bf[nb][nl + 2]);
                }
        }
    }
#undef LOAD_CHUNK

    if (EPI == 0) {
#pragma unroll
        for (int mi = 0; mi < 4; mi++) {
            const int r0 = m0 + wm * 64 + mi * 16 + (lane >> 2);
#pragma unroll
            for (int ni = 0; ni < 4; ni++) {
                const int cc = n0 + wn * 32 + ni * 8 + (lane & 3) * 2;
                *(float2*)(C + (size_t)r0 * DMODEL + cc)       = make_float2(acc[mi][ni][0], acc[mi][ni][1]);
                *(float2*)(C + (size_t)(r0 + 8) * DMODEL + cc) = make_float2(acc[mi][ni][2], acc[mi][ni][3]);
            }
        }
    } else {
        __half* dst;
        int nb0;
        if (n0 < 512)       { dst = Q16; nb0 = n0; }
        else if (n0 < 1024) { dst = K16; nb0 = n0 - 512; }
        else                { dst = V16; nb0 = n0 - 1024; }
#pragma unroll
        for (int mi = 0; mi < 4; mi++) {
            const int r0 = m0 + wm * 64 + mi * 16 + (lane >> 2);
#pragma unroll
            for (int ni = 0; ni < 4; ni++) {
                const int cc = nb0 + wn * 32 + ni * 8 + (lane & 3) * 2;
                *(__half2*)(dst + (size_t)r0 * DMODEL + cc) =
                    __floats2half2_rn(acc[mi][ni][0], acc[mi][ni][1]);
                *(__half2*)(dst + (size_t)(r0 + 8) * DMODEL + cc) =
                    __floats2half2_rn(acc[mi][ni][2], acc[mi][ni][3]);
            }
        }
    }
}

__global__ __launch_bounds__(256, 2)
void gemm_qkv(const __half* __restrict__ A, const __half* __restrict__ B,
              __half* __restrict__ Q16, __half* __restrict__ K16,
              __half* __restrict__ V16, int moffs)
{
    gemm_core<1>(A, B, nullptr, Q16, K16, V16, moffs);
}

__global__ __launch_bounds__(256, 2)
void gemm_out(const __half* __restrict__ A, const __half* __restrict__ B,
              float* __restrict__ C, int moffs)
{
    gemm_core<0>(A, B, C, nullptr, nullptr, nullptr, moffs);
}

// ---------------------------------------------------------------------------
// Neighbor attention: K staged via cp.async (33 KB smem), V gathered directly
// from L2 per-warp (first 16 rows prefetched before softmax). One CTA per s;
// batch index passed as param. 8 warps = 8 heads. q fp16 in, output fp16.
// ---------------------------------------------------------------------------
#define PITCH_H 520                          // halves; row stride 1040 B
#define ATT_SMEM (WNBR * PITCH_H * 2)        // 33280 B

__global__ __launch_bounds__(256, 6)
void attn_kernel(const __half* __restrict__ q16,
                 const __half* __restrict__ k16,
                 const __half* __restrict__ v16,
                 const int*   __restrict__ nidx,
                 __half* __restrict__ a16, int b)
{
    extern __shared__ char smc[];
    const uint32_t sbase = smem_to_u32(smc);
    __shared__ int   sj[WNBR];
    __shared__ float sq[DMODEL];

    const int s    = blockIdx.x;
    const int bs   = b * S_LEN + s;
    const int t    = threadIdx.x;
    const int h    = t >> 5;
    const int lane = t & 31;

    if (t < WNBR) sj[t] = nidx[s * WNBR + t];
    {
        __half2 qh = *(const __half2*)(q16 + (size_t)bs * DMODEL + t * 2);
        float2 qf = __half22float2(qh);
        sq[t * 2]     = qf.x;
        sq[t * 2 + 1] = qf.y;
    }
    __syncthreads();

    // Stage K rows: 32 rows x 1024 B, 64 16B-chunks per row, 8 per thread.
#pragma unroll
    for (int i = 0; i < 8; i++) {
        int e = t + i * 256;
        int w = e >> 6, c = e & 63;
        size_t src = (size_t)(b * S_LEN + sj[w]) * DMODEL + c * 8;
        CP_ASYNC16(sbase + (uint32_t)(w * 1040 + c * 16), k16 + src);
    }
    CP_COMMIT();
    CP_WAIT0();
    __syncthreads();

    // Scores: lane owns neighbor `lane`
    float acc = 0.0f;
    {
        const char* kr = smc + lane * 1040 + h * 128;
        const float* qr = sq + h * DHEAD;
#pragma unroll
        for (int i = 0; i < 8; i++) {
            uint4 kv = *(const uint4*)(kr + i * 16);
            float4 q0 = *(const float4*)(qr + i * 8);
            float4 q1 = *(const float4*)(qr + i * 8 + 4);
            float2 f0 = __half22float2(*(__half2*)&kv.x);
            float2 f1 = __half22float2(*(__half2*)&kv.y);
            float2 f2 = __half22float2(*(__half2*)&kv.z);
            float2 f3 = __half22float2(*(__half2*)&kv.w);
            acc += q0.x * f0.x + q0.y * f0.y + q0.z * f1.x + q0.w * f1.y
                 + q1.x * f2.x + q1.y * f2.y + q1.z * f3.x + q1.w * f3.y;
        }
    }
    float score = acc * 0.125f;

    // Prefetch V rows 0..15 (depend only on sj) before the softmax chain
    const __half* vbase = v16 + (size_t)b * S_LEN * DMODEL + h * DHEAD + lane * 2;
    float2 vpre[16];
#pragma unroll
    for (int u = 0; u < 16; u++)
        vpre[u] = __half22float2(*(const __half2*)(vbase + (size_t)sj[u] * DMODEL));

    // Warp softmax
    float m = score;
#pragma unroll
    for (int o = 16; o; o >>= 1) m = fmaxf(m, __shfl_xor_sync(0xffffffffu, m, o));
    float e = __expf(score - m);
    float ssum = e;
#pragma unroll
    for (int o = 16; o; o >>= 1) ssum += __shfl_xor_sync(0xffffffffu, ssum, o);
    float p = e / ssum;

    // PV: prefetched rows, then the remaining two 8-deep batches
    float ox = 0.0f, oy = 0.0f;
#pragma unroll
    for (int u = 0; u < 16; u++) {
        float pw = __shfl_sync(0xffffffffu, p, u);
        ox += pw * vpre[u].x;
        oy += pw * vpre[u].y;
    }
#pragma unroll
    for (int w0 = 16; w0 < WNBR; w0 += 8) {
        float2 vv[8];
#pragma unroll
        for (int u = 0; u < 8; u++)
            vv[u] = __half22float2(*(const __half2*)(vbase + (size_t)sj[w0 + u] * DMODEL));
#pragma unroll
        for (int u = 0; u < 8; u++) {
            float pw = __shfl_sync(0xffffffffu, p, w0 + u);
            ox += pw * vv[u].x;
            oy += pw * vv[u].y;
        }
    }

    // fp16 output (feeds final GEMM directly)
    const size_t oidx = (size_t)bs * DMODEL + h * DHEAD + lane * 2;
    *(__half2*)(a16 + oidx) = __floats2half2_rn(ox, oy);
}

// ---------------------------------------------------------------------------
// Launch: two batch-chains on two streams.
//   s0: prep -> qkv(b0) -> qkv(b1) -> attn(b1) -> out(b1) -> waitEv(chain0)
//   s1: waitEv(qkv b0)  -> attn(b0) -> out(b0) -> record chain0
// attn(b0) overlaps qkv(b1) (L2-bound vs tensor-bound); out(b0) overlaps attn(b1).
// Disjoint row ranges: attn(b0) writes x16[0:4096) while qkv(b1) reads x16[4096:8192).
// ---------------------------------------------------------------------------
extern "C" void kernel_launch(void* const* d_in, const int* in_sizes, int n_in,
                              void* d_out, int out_size)
{
    const float* x    = (const float*)d_in[0];
    const float* Wq   = (const float*)d_in[1];
    const float* Wk   = (const float*)d_in[2];
    const float* Wv   = (const float*)d_in[3];
    const float* Wo   = (const float*)d_in[4];
    const int*   nidx = (const int*)  d_in[5];
    float*       out  = (float*)d_out;

    __half *q16, *k16, *v16, *x16, *w16;
    cudaGetSymbolAddress((void**)&q16, g_q16);
    cudaGetSymbolAddress((void**)&k16, g_k16);
    cudaGetSymbolAddress((void**)&v16, g_v16);
    cudaGetSymbolAddress((void**)&x16, g_x16);
    cudaGetSymbolAddress((void**)&w16, g_w16);

    static cudaStream_t s1 = nullptr;
    static cudaEvent_t evQ0 = nullptr, evC0 = nullptr;
    if (!s1) {
        cudaStreamCreateWithFlags(&s1, cudaStreamNonBlocking);
        cudaEventCreateWithFlags(&evQ0, cudaEventDisableTiming);
        cudaEventCreateWithFlags(&evC0, cudaEventDisableTiming);
        cudaFuncSetAttribute(attn_kernel, cudaFuncAttributeMaxDynamicSharedMemorySize, ATT_SMEM);
        cudaFuncSetAttribute(gemm_qkv,    cudaFuncAttributeMaxDynamicSharedMemorySize, GEMM_SMEM);
        cudaFuncSetAttribute(gemm_out,    cudaFuncAttributeMaxDynamicSharedMemorySize, GEMM_SMEM);
    }

    const int NW = DMODEL * DMODEL;           // 262144
    dim3 qkvgrid(3 * DMODEL / 128, S_LEN / 128);   // (12, 32) per batch
    dim3 ogrid(DMODEL / 128, S_LEN / 128);         // (4, 32) per batch

    // ---- stream 0: prep, qkv(b0) ----
    prep_kernel<<<(NX4 + 4 * NW4) / 256, 256, 0, 0>>>(x, Wq, Wk, Wv, Wo, x16, w16);
    gemm_qkv<<<qkvgrid, 256, GEMM_SMEM, 0>>>(x16, w16, q16, k16, v16, 0);
    cudaEventRecord(evQ0, 0);

    // ---- stream 0 continues: qkv(b1), attn(b1), out(b1) ----
    gemm_qkv<<<qkvgrid, 256, GEMM_SMEM, 0>>>(x16, w16, q16, k16, v16, S_LEN);

    // ---- stream 1: batch-0 chain, forked after qkv(b0) ----
    cudaStreamWaitEvent(s1, evQ0, 0);
    attn_kernel<<<S_LEN, 256, ATT_SMEM, s1>>>(q16, k16, v16, nidx, x16, 0);
    gemm_out<<<ogrid, 256, GEMM_SMEM, s1>>>(x16, w16 + 3 * NW, out, 0);
    cudaEventRecord(evC0, s1);

    attn_kernel<<<S_LEN, 256, ATT_SMEM, 0>>>(q16, k16, v16, nidx, x16, 1);
    gemm_out<<<ogrid, 256, GEMM_SMEM, 0>>>(x16, w16 + 3 * NW, out, S_LEN);

    // join batch-0 chain back into the capture's terminal stream
    cudaStreamWaitEvent((cudaStream_t)0, evC0, 0);
}